// round 6
// baseline (speedup 1.0000x reference)
#include <cuda_runtime.h>
#include <cstdint>

// Problem constants
#define N_FEAT  65536
#define N_PROTO 512
#define DIMK    256

#define BLK_M   128                 // feature rows per CTA
#define BLK_N   64                  // prototypes per chunk
#define N_CHUNKS (N_PROTO / BLK_N)  // 8
#define K_STEPS  (DIMK / 8)         // 32 k-steps of k=8

// SMEM layout (bytes)
#define SM_FSQ   0                        // 128 floats
#define SM_PSQ   512                      // 64 floats
#define SM_A     1024                     // A frags: 8 mtiles * 32 s * 32 lanes * 16B = 131072
#define SM_B     (SM_A + 131072)          // B frags: 8 ntiles * 32 s * 32 lanes * 8B = 65536
#define SM_T     (SM_B + 65536)           // transpose buffer 64 x 132 floats = 33792
#define TB_STRIDE 132
#define SMEM_TOTAL (SM_T + BLK_N * TB_STRIDE * 4)   // 231424 B

// fp32 -> tf32 (round to nearest)
__device__ __forceinline__ uint32_t f2tf32(float f) {
    uint32_t r;
    asm("cvt.rna.tf32.f32 %0, %1;" : "=r"(r) : "f"(f));
    return r;
}

// m16n8k8 tf32 MMA (legacy tensor path; no 'a' arch feature needed)
__device__ __forceinline__ void mma_tf32(float d[4], const uint32_t a[4], const uint32_t b[2]) {
    asm volatile(
        "mma.sync.aligned.m16n8k8.row.col.f32.tf32.tf32.f32 "
        "{%0,%1,%2,%3}, {%4,%5,%6,%7}, {%8,%9}, {%0,%1,%2,%3};"
        : "+f"(d[0]), "+f"(d[1]), "+f"(d[2]), "+f"(d[3])
        : "r"(a[0]), "r"(a[1]), "r"(a[2]), "r"(a[3]),
          "r"(b[0]), "r"(b[1]));
}

// ---------------------------------------------------------------------------
// Single fused kernel:
//   - stage A tile (128x256) as tf32 fragments in SMEM (+ exact fp32 feat norms)
//   - per 64-proto chunk: stage B fragments (+ exact proto norms), mma.sync
//     mainloop, fused distance epilogue writing [N,P] directly and [P,N] via
//     a padded SMEM transpose buffer.
//
// Fragment storage (both sides agree):
//   A: float4 slot per (mtile t, kstep s, lane'), regs a0..a3 in the 4 floats.
//      lane'(g, tig) = g*4 + (tig ^ ((g>>1)&3))          (bank de-conflict)
//   B: float2 slot per (ntile u, kstep s, lane'), regs b0,b1.
//      lane'(g, tig, s) = g*4 + (tig ^ (((s>>3)&3) ^ (((g>>2)&1)<<1)))
// ---------------------------------------------------------------------------
__global__ void __launch_bounds__(256, 1) proto_dist_kernel(
    const float* __restrict__ feat,
    const float* __restrict__ proto,
    float* __restrict__ out1,    // [N, P]
    float* __restrict__ out2)    // [P, N]
{
    extern __shared__ char smem[];
    float*    s_fsq  = (float*)(smem + SM_FSQ);
    float*    s_psq  = (float*)(smem + SM_PSQ);
    float*    s_A    = (float*)(smem + SM_A);
    uint32_t* s_Bu   = (uint32_t*)(smem + SM_B);
    float*    s_T    = (float*)(smem + SM_T);
    float*    s_part = s_T;   // reuse transpose buffer for norm partials

    const int tid = threadIdx.x;
    const int m0  = blockIdx.x * BLK_M;

    // ---- Stage A tile as tf32 fragments + exact fp32 feature norms ----
    {
        const int row = tid >> 1, half = tid & 1;
        const int t = row >> 4, r = row & 15, gg = r & 7, hi = r >> 3;
        const int fA = (gg >> 1) & 3;
        const float4* src = (const float4*)(feat + (size_t)(m0 + row) * DIMK) + half * 32;
        float ss = 0.f;
#pragma unroll
        for (int jj = 0; jj < 32; jj++) {
            float4 v = src[jj];
            ss += v.x * v.x + v.y * v.y + v.z * v.z + v.w * v.w;
            const int s   = half * 16 + (jj >> 1);
            const int reg = hi + 2 * (jj & 1);      // a0/a1 (k<4) or a2/a3 (k>=4)
            uint32_t* slab = (uint32_t*)(s_A + (t * 32 + s) * 128);
            slab[(gg * 4 + (0 ^ fA)) * 4 + reg] = f2tf32(v.x);
            slab[(gg * 4 + (1 ^ fA)) * 4 + reg] = f2tf32(v.y);
            slab[(gg * 4 + (2 ^ fA)) * 4 + reg] = f2tf32(v.z);
            slab[(gg * 4 + (3 ^ fA)) * 4 + reg] = f2tf32(v.w);
        }
        s_part[tid] = ss;
    }
    __syncthreads();
    if (tid < BLK_M) s_fsq[tid] = s_part[2 * tid] + s_part[2 * tid + 1];
    // (visibility of s_fsq guaranteed by the sync after B staging below)

    // Per-thread MMA identity
    const int lane = tid & 31, wid = tid >> 5;
    const int mi = wid >> 1, nj = wid & 1;        // warp grid: 4 (M) x 2 (N)
    const int g = lane >> 2, tig = lane & 3;
    const int laneA = g * 4 + (tig ^ ((g >> 1) & 3));
    const int gb2 = ((g >> 2) & 1) << 1;

    const float4* psrc4 = (const float4*)proto;

    for (int chunk = 0; chunk < N_CHUNKS; chunk++) {
        const int p0 = chunk * BLK_N;

        // ---- Stage B chunk as tf32 fragments + exact fp32 proto norms ----
        {
            const int prow = tid >> 2, q = tid & 3;
            const int u = prow >> 3, gg = prow & 7;
            const size_t rb = (size_t)(p0 + prow) * (DIMK / 4);
            float ss = 0.f;
#pragma unroll
            for (int m = 0; m < 8; m++) {
                const int s = q * 8 + m;
                float4 f0 = psrc4[rb + q * 16 + 2 * m];      // k = 8s..8s+3
                float4 f1 = psrc4[rb + q * 16 + 2 * m + 1];  // k = 8s+4..8s+7
                ss += f0.x * f0.x + f0.y * f0.y + f0.z * f0.z + f0.w * f0.w
                    + f1.x * f1.x + f1.y * f1.y + f1.z * f1.z + f1.w * f1.w;
                const int h = ((s >> 3) & 3) ^ (((gg >> 2) & 1) << 1);
                uint32_t* slab = s_Bu + (u * 32 + s) * 64;
                const float v0[4] = {f0.x, f0.y, f0.z, f0.w};
                const float v1[4] = {f1.x, f1.y, f1.z, f1.w};
#pragma unroll
                for (int e = 0; e < 4; e++) {
                    const int slot = gg * 4 + (e ^ h);
                    uint2 pk;
                    pk.x = f2tf32(v0[e]);   // b0
                    pk.y = f2tf32(v1[e]);   // b1
                    *((uint2*)(slab + slot * 2)) = pk;
                }
            }
            ss += __shfl_xor_sync(0xffffffffu, ss, 1);
            ss += __shfl_xor_sync(0xffffffffu, ss, 2);
            if (q == 0) s_psq[prow] = ss;
        }
        __syncthreads();   // (a) B frags + psq (+ fsq on chunk 0) visible

        // ---- MMA mainloop: 128x64 tile, K=256 ----
        float acc[2][4][4];
#pragma unroll
        for (int tp = 0; tp < 2; tp++)
#pragma unroll
            for (int up = 0; up < 4; up++)
#pragma unroll
                for (int c = 0; c < 4; c++) acc[tp][up][c] = 0.f;

#pragma unroll
        for (int s8 = 0; s8 < 4; s8++) {
            const int slotB = g * 4 + (tig ^ (s8 ^ gb2));
#pragma unroll
            for (int sl = 0; sl < 8; sl++) {
                const int s = s8 * 8 + sl;
                uint4 a[2];
#pragma unroll
                for (int tp = 0; tp < 2; tp++)
                    a[tp] = *((const uint4*)(s_A + ((mi * 2 + tp) * 32 + s) * 128) + laneA);
                uint2 b[4];
#pragma unroll
                for (int up = 0; up < 4; up++)
                    b[up] = *((const uint2*)s_Bu + ((nj * 4 + up) * 32 + s) * 32 + slotB);
#pragma unroll
                for (int tp = 0; tp < 2; tp++)
#pragma unroll
                    for (int up = 0; up < 4; up++)
                        mma_tf32(acc[tp][up], (const uint32_t*)&a[tp], (const uint32_t*)&b[up]);
            }
        }

        // ---- Fused distance epilogue ----
        {
            float fs[2][2];
#pragma unroll
            for (int tp = 0; tp < 2; tp++) {
                fs[tp][0] = s_fsq[mi * 32 + tp * 16 + g];
                fs[tp][1] = s_fsq[mi * 32 + tp * 16 + g + 8];
            }
#pragma unroll
            for (int tp = 0; tp < 2; tp++) {
#pragma unroll
                for (int up = 0; up < 4; up++) {
                    const int pl = nj * 32 + up * 8 + 2 * tig;
                    const float ps0 = s_psq[pl], ps1 = s_psq[pl + 1];
                    const float d0 = fs[tp][0] + ps0 - 2.0f * acc[tp][up][0];
                    const float d1 = fs[tp][0] + ps1 - 2.0f * acc[tp][up][1];
                    const float d2 = fs[tp][1] + ps0 - 2.0f * acc[tp][up][2];
                    const float d3 = fs[tp][1] + ps1 - 2.0f * acc[tp][up][3];
                    const int ml0 = mi * 32 + tp * 16 + g, ml1 = ml0 + 8;
                    // out1 [N,P]: full 32B sectors per 4-lane group
                    *(float2*)(out1 + (size_t)(m0 + ml0) * N_PROTO + p0 + pl) = make_float2(d0, d1);
                    *(float2*)(out1 + (size_t)(m0 + ml1) * N_PROTO + p0 + pl) = make_float2(d2, d3);
                    // transpose buffer (stride 132 -> conflict-free)
                    s_T[(size_t)pl * TB_STRIDE + ml0]       = d0;
                    s_T[(size_t)(pl + 1) * TB_STRIDE + ml0] = d1;
                    s_T[(size_t)pl * TB_STRIDE + ml1]       = d2;
                    s_T[(size_t)(pl + 1) * TB_STRIDE + ml1] = d3;
                }
            }
        }
        __syncthreads();   // (c) tbuf complete; B-frag reads done

        // ---- out2 [P,N]: coalesced 128B-per-thread stores ----
        {
            const int p = tid >> 2, seg = tid & 3;
            const float4* src = (const float4*)(s_T + p * TB_STRIDE + seg * 32);
            float4* dst = (float4*)(out2 + (size_t)(p0 + p) * N_FEAT + m0 + seg * 32);
#pragma unroll
            for (int i = 0; i < 8; i++) dst[i] = src[i];
        }
        // next iteration's sync (a) separates these reads from tbuf/B reuse
    }
}

// ---------------------------------------------------------------------------
// Launch
// ---------------------------------------------------------------------------
extern "C" void kernel_launch(void* const* d_in, const int* in_sizes, int n_in,
                              void* d_out, int out_size)
{
    (void)in_sizes; (void)n_in; (void)out_size;
    const float* feat  = (const float*)d_in[0];
    const float* proto = (const float*)d_in[1];
    float* out1 = (float*)d_out;
    float* out2 = out1 + (size_t)N_FEAT * N_PROTO;

    cudaFuncSetAttribute(proto_dist_kernel,
                         cudaFuncAttributeMaxDynamicSharedMemorySize, SMEM_TOTAL);

    proto_dist_kernel<<<N_FEAT / BLK_M, 256, SMEM_TOTAL>>>(feat, proto, out1, out2);
}

// round 7
// speedup vs baseline: 1.6333x; 1.6333x over previous
#include <cuda_runtime.h>
#include <cuda_fp16.h>
#include <cstdint>

// Problem constants
#define N_FEAT  65536
#define N_PROTO 512
#define DIMK    256

#define BLK_M   256                 // feature rows per CTA
#define BLK_N   64                  // prototypes per chunk
#define N_CHUNKS (N_PROTO / BLK_N)  // 8

// SMEM layout (bytes)
#define SM_FSQ   0                          // 256 floats = 1024 B
#define SM_PSQ   1024                       // 512 floats = 2048 B
#define SM_A     4096                       // 16 mtiles * 16 ksteps * 512 B = 131072
#define SM_B     (SM_A + 131072)            // 2 bufs * 8 ntiles * 16 ksteps * 256 B = 65536
#define B_BUF_BYTES 32768
#define SMEM_TOTAL (SM_B + 2 * B_BUF_BYTES) // 200704 B

// pack float2 -> fp16x2 (x -> low half)
__device__ __forceinline__ uint32_t pk(float2 f) {
    __half2 h = __floats2half2_rn(f.x, f.y);
    return *(uint32_t*)&h;
}

// m16n8k16 fp16 MMA, fp32 accumulate (sm_80+ legacy tensor path)
__device__ __forceinline__ void mma_f16(float d[4], const uint32_t a[4], const uint32_t b[2]) {
    asm volatile(
        "mma.sync.aligned.m16n8k16.row.col.f32.f16.f16.f32 "
        "{%0,%1,%2,%3}, {%4,%5,%6,%7}, {%8,%9}, {%0,%1,%2,%3};"
        : "+f"(d[0]), "+f"(d[1]), "+f"(d[2]), "+f"(d[3])
        : "r"(a[0]), "r"(a[1]), "r"(a[2]), "r"(a[3]),
          "r"(b[0]), "r"(b[1]));
}

// ---------------------------------------------------------------------------
// Fragment SMEM layout (identity lane mapping, no swizzle, conflict-free):
//   A slab (mtile t, kstep s): 32 lanes x uint4 {a0,a1,a2,a3} = 512 B
//     lane (g=lane>>2, tig=lane&3): a0={A[g][2tig],A[g][2tig+1]},
//     a1=rows+8, a2/a3 = k+8 — PTX m16n8k16 row-major A layout.
//   B slab (ntile u, kstep s): 32 lanes x uint2 {b0,b1} = 256 B
//     b0={B[2tig][g],B[2tig+1][g]}, b1 = k+8 — col-major B layout.
// Staging threads gather the FULL slot -> STS.128/STS.64, linear addresses.
// ---------------------------------------------------------------------------
__global__ void __launch_bounds__(512, 1) proto_dist_kernel(
    const float* __restrict__ feat,
    const float* __restrict__ proto,
    float* __restrict__ out1,    // [N, P]
    float* __restrict__ out2)    // [P, N]
{
    extern __shared__ char smem[];
    float* s_fsq = (float*)(smem + SM_FSQ);
    float* s_psq = (float*)(smem + SM_PSQ);

    const int tid  = threadIdx.x;
    const int lane = tid & 31;
    const int wid  = tid >> 5;
    const int g    = lane >> 2;
    const int tig  = lane & 3;
    const int m0   = blockIdx.x * BLK_M;

    // ---- Stage A tile (256 x 256) as fp16 fragments + exact fp32 feat norms ----
    // warp w handles mtile t = w; each thread builds slot (t, s, lane) for all s.
    {
        const int t = wid;
        const float* rA = feat + (size_t)(m0 + t * 16 + g) * DIMK;
        const float* rB = rA + 8 * DIMK;
        float sqA = 0.f, sqB = 0.f;
#pragma unroll
        for (int s = 0; s < 16; s++) {
            const int kA = s * 16 + 2 * tig;
            float2 f0 = *(const float2*)(rA + kA);
            float2 f1 = *(const float2*)(rB + kA);
            float2 f2 = *(const float2*)(rA + kA + 8);
            float2 f3 = *(const float2*)(rB + kA + 8);
            sqA += f0.x * f0.x + f0.y * f0.y + f2.x * f2.x + f2.y * f2.y;
            sqB += f1.x * f1.x + f1.y * f1.y + f3.x * f3.x + f3.y * f3.y;
            uint4 w;
            w.x = pk(f0); w.y = pk(f1); w.z = pk(f2); w.w = pk(f3);
            *(uint4*)(smem + SM_A + (size_t)((t * 16 + s) * 32 + lane) * 16) = w;
        }
        // reduce over tig (k-slices 2tig,2tig+1,2tig+8,2tig+9 per kstep cover full row)
        sqA += __shfl_xor_sync(0xffffffffu, sqA, 1);
        sqA += __shfl_xor_sync(0xffffffffu, sqA, 2);
        sqB += __shfl_xor_sync(0xffffffffu, sqB, 1);
        sqB += __shfl_xor_sync(0xffffffffu, sqB, 2);
        if (tig == 0) {
            s_fsq[t * 16 + g]     = sqA;
            s_fsq[t * 16 + g + 8] = sqB;
        }
    }

    // ---- All 512 prototype norms, exact fp32 (proto is L2-hot: 512 KB) ----
    {
        const float4* r = (const float4*)(proto + (size_t)tid * DIMK);
        float s0 = 0.f, s1 = 0.f, s2 = 0.f, s3 = 0.f;
#pragma unroll
        for (int j = 0; j < 64; j += 4) {
            float4 v0 = r[j], v1 = r[j + 1], v2 = r[j + 2], v3 = r[j + 3];
            s0 += v0.x * v0.x + v0.y * v0.y + v0.z * v0.z + v0.w * v0.w;
            s1 += v1.x * v1.x + v1.y * v1.y + v1.z * v1.z + v1.w * v1.w;
            s2 += v2.x * v2.x + v2.y * v2.y + v2.z * v2.z + v2.w * v2.w;
            s3 += v3.x * v3.x + v3.y * v3.y + v3.z * v3.z + v3.w * v3.w;
        }
        s_psq[tid] = (s0 + s1) + (s2 + s3);
    }

    // ---- B staging lambda: chunk c into buffer b ----
    const int bu = tid >> 6;          // ntile 0..7
    const int bh = (tid >> 5) & 1;    // kstep half
    auto stage_B = [&](int c, int b) {
        const float* r = proto + (size_t)(c * BLK_N + bu * 8 + g) * DIMK;
        char* dst = smem + SM_B + b * B_BUF_BYTES;
#pragma unroll
        for (int ss = 0; ss < 8; ss++) {
            const int s  = bh * 8 + ss;
            const int kA = s * 16 + 2 * tig;
            float2 f0 = *(const float2*)(r + kA);
            float2 f1 = *(const float2*)(r + kA + 8);
            uint2 w;
            w.x = pk(f0); w.y = pk(f1);
            *(uint2*)(dst + (size_t)((bu * 16 + s) * 32 + lane) * 8) = w;
        }
    };

    stage_B(0, 0);

    // Warp grid: 8 (M) x 2 (N); per warp T=2 mtiles, U=4 ntiles
    const int mi = wid >> 1;
    const int nj = wid & 1;

    for (int c = 0; c < N_CHUNKS; c++) {
        __syncthreads();   // frags(buf c&1) + norms visible; buf (c+1)&1 free to rewrite

        const int p0 = c * BLK_N;
        const char* Bbuf = smem + SM_B + (c & 1) * B_BUF_BYTES;

        float acc[2][4][4];
#pragma unroll
        for (int tp = 0; tp < 2; tp++)
#pragma unroll
            for (int up = 0; up < 4; up++)
#pragma unroll
                for (int e = 0; e < 4; e++) acc[tp][up][e] = 0.f;

#pragma unroll
        for (int s = 0; s < 16; s++) {
            uint4 a[2];
#pragma unroll
            for (int tp = 0; tp < 2; tp++)
                a[tp] = *(const uint4*)(smem + SM_A +
                         (size_t)(((mi * 2 + tp) * 16 + s) * 32 + lane) * 16);
            uint2 b[4];
#pragma unroll
            for (int up = 0; up < 4; up++)
                b[up] = *(const uint2*)(Bbuf +
                         (size_t)(((nj * 4 + up) * 16 + s) * 32 + lane) * 8);
#pragma unroll
            for (int tp = 0; tp < 2; tp++)
#pragma unroll
                for (int up = 0; up < 4; up++)
                    mma_f16(acc[tp][up], (const uint32_t*)&a[tp], (const uint32_t*)&b[up]);
        }

        // ---- Fused distance epilogue: direct stores for BOTH outputs ----
#pragma unroll
        for (int tp = 0; tp < 2; tp++) {
            const int ml0 = mi * 32 + tp * 16 + g;
            const int ml1 = ml0 + 8;
            const float fs0 = s_fsq[ml0];
            const float fs1 = s_fsq[ml1];
#pragma unroll
            for (int up = 0; up < 4; up++) {
                const int pl = nj * 32 + up * 8 + 2 * tig;
                const float ps0 = s_psq[p0 + pl];
                const float ps1 = s_psq[p0 + pl + 1];
                const float d0 = fs0 + ps0 - 2.0f * acc[tp][up][0];
                const float d1 = fs0 + ps1 - 2.0f * acc[tp][up][1];
                const float d2 = fs1 + ps0 - 2.0f * acc[tp][up][2];
                const float d3 = fs1 + ps1 - 2.0f * acc[tp][up][3];
                // out1 [N,P]: 4 tig-lanes x float2 = full 32B sector per row
                *(float2*)(out1 + (size_t)(m0 + ml0) * N_PROTO + p0 + pl) = make_float2(d0, d1);
                *(float2*)(out1 + (size_t)(m0 + ml1) * N_PROTO + p0 + pl) = make_float2(d2, d3);
                // out2 [P,N]: 8 g-lanes x 4B = full 32B sector per column
                out2[(size_t)(p0 + pl)     * N_FEAT + m0 + ml0] = d0;
                out2[(size_t)(p0 + pl + 1) * N_FEAT + m0 + ml0] = d1;
                out2[(size_t)(p0 + pl)     * N_FEAT + m0 + ml1] = d2;
                out2[(size_t)(p0 + pl + 1) * N_FEAT + m0 + ml1] = d3;
            }
        }

        // overlap next chunk's B staging with other warps still in mainloop/epilogue
        if (c + 1 < N_CHUNKS) stage_B(c + 1, (c + 1) & 1);
    }
}

// ---------------------------------------------------------------------------
// Launch
// ---------------------------------------------------------------------------
extern "C" void kernel_launch(void* const* d_in, const int* in_sizes, int n_in,
                              void* d_out, int out_size)
{
    (void)in_sizes; (void)n_in; (void)out_size;
    const float* feat  = (const float*)d_in[0];
    const float* proto = (const float*)d_in[1];
    float* out1 = (float*)d_out;
    float* out2 = out1 + (size_t)N_FEAT * N_PROTO;

    cudaFuncSetAttribute(proto_dist_kernel,
                         cudaFuncAttributeMaxDynamicSharedMemorySize, SMEM_TOTAL);

    proto_dist_kernel<<<N_FEAT / BLK_M, 512, SMEM_TOTAL>>>(feat, proto, out1, out2);
}